// round 6
// baseline (speedup 1.0000x reference)
#include <cuda_runtime.h>
#include <cstdint>

#define VOCAB 67
#define EMB 50
#define NLAYERS 8
#define REP_FLOATS 4824       // 67 rows * 72 floats
#define TAB_FLOATS (4*REP_FLOATS)

// Precomputed per-token logits, stored as 4 shifted replicas:
// replica j stores row element e at padded position e + pad_j (pads 0,3,2,1), rows 72 floats.
__device__ __align__(16) float g_tab[TAB_FLOATS];

// ---------------------------------------------------------------------------
// cp.async helpers
// ---------------------------------------------------------------------------
__device__ __forceinline__ void cp16(uint32_t s, const void* g) {
    asm volatile("cp.async.cg.shared.global [%0], [%1], 16;" :: "r"(s), "l"(g));
}
__device__ __forceinline__ void cp_commit() { asm volatile("cp.async.commit_group;"); }
template<int N> __device__ __forceinline__ void cp_wait() {
    asm volatile("cp.async.wait_group %0;" :: "n"(N));
}

// ---------------------------------------------------------------------------
// Kernel 1: per-token logits table. Block t handles token t.
// Double-buffered cp.async staging of each layer's K/P; threads 0-49 real,
// 64-113 imag; 4-way split accumulators. Triggers PDL completion at entry
// so the gather kernel's prologue can overlap.
// ---------------------------------------------------------------------------
__global__ void __launch_bounds__(128) table_kernel(
    const float* __restrict__ emb,   // [67,50]
    const float* __restrict__ kappa, // [8,50,50]
    const float* __restrict__ phi,   // [8,50,50]
    const float* __restrict__ W_out, // [50,67]
    const float* __restrict__ b_out) // [67]
{
    cudaTriggerProgrammaticLaunchCompletion();

    const int t   = blockIdx.x;
    const int tid = threadIdx.x;

    __shared__ __align__(16) float wK[2][EMB*EMB], wP[2][EMB*EMB];  // 40 KB
    __shared__ float sar[2][EMB], sai[2][EMB], sint[EMB];

    const uint32_t sK0 = (uint32_t)__cvta_generic_to_shared(&wK[0][0]);
    const uint32_t sK1 = (uint32_t)__cvta_generic_to_shared(&wK[1][0]);
    const uint32_t sP0 = (uint32_t)__cvta_generic_to_shared(&wP[0][0]);
    const uint32_t sP1 = (uint32_t)__cvta_generic_to_shared(&wP[1][0]);

    if (tid < EMB) { sar[0][tid] = emb[t*EMB + tid]; sai[0][tid] = 0.f; }

    // prefetch layer 0 into buffer 0
    #pragma unroll
    for (int i = 0; i < 5; ++i) {
        int j = tid + i*128;
        if (j < 625) {
            cp16(sK0 + j*16, kappa + j*4);
            cp16(sP0 + j*16, phi   + j*4);
        }
    }
    cp_commit();

    for (int l = 0; l < NLAYERS; ++l) {
        const int buf = l & 1;
        if (l + 1 < NLAYERS) {
            const uint32_t dK = (buf ? sK0 : sK1), dP = (buf ? sP0 : sP1);
            const float* gK = kappa + (l+1)*EMB*EMB;
            const float* gP = phi   + (l+1)*EMB*EMB;
            #pragma unroll
            for (int i = 0; i < 5; ++i) {
                int j = tid + i*128;
                if (j < 625) {
                    cp16(dK + j*16, gK + j*4);
                    cp16(dP + j*16, gP + j*4);
                }
            }
            cp_commit();
            cp_wait<1>();
        } else {
            cp_wait<0>();
        }
        __syncthreads();

        const int cur = l & 1, nxt = cur ^ 1;
        const float* K = wK[buf];
        const float* P = wP[buf];
        if (tid < EMB) {                       // real, f = tid
            float a0=0.f,a1=0.f,a2=0.f,a3=0.f;
            #pragma unroll
            for (int e = 0; e < 48; e += 4) {
                a0 += sar[cur][e+0]*K[(e+0)*EMB+tid] - sai[cur][e+0]*P[(e+0)*EMB+tid];
                a1 += sar[cur][e+1]*K[(e+1)*EMB+tid] - sai[cur][e+1]*P[(e+1)*EMB+tid];
                a2 += sar[cur][e+2]*K[(e+2)*EMB+tid] - sai[cur][e+2]*P[(e+2)*EMB+tid];
                a3 += sar[cur][e+3]*K[(e+3)*EMB+tid] - sai[cur][e+3]*P[(e+3)*EMB+tid];
            }
            a0 += sar[cur][48]*K[48*EMB+tid] - sai[cur][48]*P[48*EMB+tid];
            a1 += sar[cur][49]*K[49*EMB+tid] - sai[cur][49]*P[49*EMB+tid];
            sar[nxt][tid] = (a0+a1) + (a2+a3);
        } else if (tid >= 64 && tid < 64 + EMB) {  // imag, f = tid-64
            const int f = tid - 64;
            float a0=0.f,a1=0.f,a2=0.f,a3=0.f;
            #pragma unroll
            for (int e = 0; e < 48; e += 4) {
                a0 += sar[cur][e+0]*P[(e+0)*EMB+f] + sai[cur][e+0]*K[(e+0)*EMB+f];
                a1 += sar[cur][e+1]*P[(e+1)*EMB+f] + sai[cur][e+1]*K[(e+1)*EMB+f];
                a2 += sar[cur][e+2]*P[(e+2)*EMB+f] + sai[cur][e+2]*K[(e+2)*EMB+f];
                a3 += sar[cur][e+3]*P[(e+3)*EMB+f] + sai[cur][e+3]*K[(e+3)*EMB+f];
            }
            a0 += sar[cur][48]*P[48*EMB+f] + sai[cur][48]*K[48*EMB+f];
            a1 += sar[cur][49]*P[49*EMB+f] + sai[cur][49]*K[49*EMB+f];
            sai[nxt][f] = (a0+a1) + (a2+a3);
        }
        __syncthreads();
    }

    // 8 layers (even): result in buffer index 0
    if (tid < EMB) {
        float a = sar[0][tid], b = sai[0][tid];
        sint[tid] = a*a + b*b;
    }
    __syncthreads();
    if (tid < VOCAB) {
        float acc = __ldg(b_out + tid);
        #pragma unroll
        for (int e = 0; e < EMB; ++e)
            acc += sint[e] * __ldg(W_out + e*VOCAB + tid);
        // 4 shifted replicas (pads: j=0->0, 1->3, 2->2, 3->1)
        g_tab[0*REP_FLOATS + t*72 + tid + 0] = acc;
        g_tab[1*REP_FLOATS + t*72 + tid + 3] = acc;
        g_tab[2*REP_FLOATS + t*72 + tid + 2] = acc;
        g_tab[3*REP_FLOATS + t*72 + tid + 1] = acc;
    }
}

// ---------------------------------------------------------------------------
// Kernel 2: gather. One warp = 32 consecutive tokens = 2144 floats = 536
// float4s (exact). Lane owns output float4 p4 = lane + 32*i -> STG.128 is
// 512B contiguous, 128B-aligned per warp (write-back: most traffic terminates
// in L2 under graph replay). Token ids packed two-per-register so each
// iteration needs ONE shfl. Main table read = one aligned LDG.128 from the
// matching shifted replica; straddles (r>=64) take one predicated fixup LDG.
// ---------------------------------------------------------------------------
__global__ void __launch_bounds__(256) gather_kernel(
    const int* __restrict__ idx, float* __restrict__ out)
{
    const int lane = threadIdx.x & 31;
    const int warp = (blockIdx.x * 256 + (int)threadIdx.x) >> 5;   // 0..16383

    // prologue (overlaps table_kernel via PDL)
    const int mytok = __ldg(idx + warp*32 + lane);       // token ids < 67 (8 bits)
    const int nxt   = __shfl_down_sync(0xffffffffu, mytok, 1);
    const int pair  = mytok | (nxt << 8);                // {tok[lane], tok[lane+1]}
    float4* O = (float4*)out + (uint32_t)warp * 536;

    cudaGridDependencySynchronize();                     // wait for g_tab

    #pragma unroll
    for (int i = 0; i < 17; ++i) {
        const int p4 = lane + 32*i;          // output float4 index
        const int e0 = 4*p4;
        const int tk = (int)((unsigned)e0 / 67u);  // owning token slot
        const int r  = e0 - 67*tk;           // element offset within token row

        const int pp     = __shfl_sync(0xffffffffu, pair, tk & 31);
        const int token  = pp & 0xff;
        const int token2 = (pp >> 8) & 0xff;

        const int j   = tk & 3;              // == r & 3 (e0 % 4 == 0)
        const int pos = (r + 3) & ~3;        // r + pad_j, 16B-aligned
        float4 v = __ldg((const float4*)(g_tab + j*REP_FLOATS + token*72 + pos));

        if (r >= 64) {                       // straddle: tail from next token
            float4 w = __ldg((const float4*)(g_tab + (j+1)*REP_FLOATS + token2*72));
            if (r == 66) v.y = w.y;
            if (r >= 65) v.z = w.z;
            v.w = w.w;
        }
        if (i < 16 || lane < 24)             // quad 536.. don't exist (i=16, lanes 24-31)
            O[p4] = v;
    }
}

// ---------------------------------------------------------------------------
// Launch: gather uses programmatic dependent launch so its prologue
// (idx loads, address setup) overlaps the tail of table_kernel.
// ---------------------------------------------------------------------------
extern "C" void kernel_launch(void* const* d_in, const int* in_sizes, int n_in,
                              void* d_out, int out_size) {
    const int*   idx = (const int*)d_in[0];   // input_seq [64,8192] int32
    const float* emb = (const float*)d_in[1]; // embedding_table [67,50]
    const float* kap = (const float*)d_in[2]; // kappa [8,50,50]
    const float* ph  = (const float*)d_in[3]; // phi   [8,50,50]
    const float* Wo  = (const float*)d_in[4]; // W_out [50,67]
    const float* bo  = (const float*)d_in[5]; // b_out [67]
    float* out = (float*)d_out;

    table_kernel<<<VOCAB, 128>>>(emb, kap, ph, Wo, bo);

    cudaLaunchConfig_t cfg = {};
    cfg.gridDim  = dim3(2048);
    cfg.blockDim = dim3(256);
    cfg.stream   = 0;
    cudaLaunchAttribute attr[1];
    attr[0].id = cudaLaunchAttributeProgrammaticStreamSerialization;
    attr[0].val.programmaticStreamSerializationAllowed = 1;
    cfg.attrs = attr;
    cfg.numAttrs = 1;
    cudaLaunchKernelEx(&cfg, gather_kernel, idx, out);
}

// round 7
// speedup vs baseline: 1.5458x; 1.5458x over previous
#include <cuda_runtime.h>
#include <cstdint>

#define VOCAB 67
#define EMB 50
#define NLAYERS 8
#define REP_FLOATS 4824       // 67 rows * 72 floats
#define TAB_FLOATS (4*REP_FLOATS)

// Precomputed per-token logits, stored as 4 shifted replicas:
// replica j stores row element e at padded position e + pad_j (pads 0,3,2,1), rows 72 floats.
__device__ __align__(16) float g_tab[TAB_FLOATS];

// ---------------------------------------------------------------------------
// cp.async helpers
// ---------------------------------------------------------------------------
__device__ __forceinline__ void cp16(uint32_t s, const void* g) {
    asm volatile("cp.async.cg.shared.global [%0], [%1], 16;" :: "r"(s), "l"(g));
}
__device__ __forceinline__ void cp_commit() { asm volatile("cp.async.commit_group;"); }
template<int N> __device__ __forceinline__ void cp_wait() {
    asm volatile("cp.async.wait_group %0;" :: "n"(N));
}

// ---------------------------------------------------------------------------
// Kernel 1: per-token logits table. Block t handles token t.
// Double-buffered cp.async staging of each layer's K/P; threads 0-49 real,
// 64-113 imag; 4-way split accumulators.
// ---------------------------------------------------------------------------
__global__ void __launch_bounds__(128) table_kernel(
    const float* __restrict__ emb,   // [67,50]
    const float* __restrict__ kappa, // [8,50,50]
    const float* __restrict__ phi,   // [8,50,50]
    const float* __restrict__ W_out, // [50,67]
    const float* __restrict__ b_out) // [67]
{
    const int t   = blockIdx.x;
    const int tid = threadIdx.x;

    __shared__ __align__(16) float wK[2][EMB*EMB], wP[2][EMB*EMB];  // 40 KB
    __shared__ float sar[2][EMB], sai[2][EMB], sint[EMB];

    const uint32_t sK0 = (uint32_t)__cvta_generic_to_shared(&wK[0][0]);
    const uint32_t sK1 = (uint32_t)__cvta_generic_to_shared(&wK[1][0]);
    const uint32_t sP0 = (uint32_t)__cvta_generic_to_shared(&wP[0][0]);
    const uint32_t sP1 = (uint32_t)__cvta_generic_to_shared(&wP[1][0]);

    if (tid < EMB) { sar[0][tid] = emb[t*EMB + tid]; sai[0][tid] = 0.f; }

    // prefetch layer 0 into buffer 0
    #pragma unroll
    for (int i = 0; i < 5; ++i) {
        int j = tid + i*128;
        if (j < 625) {
            cp16(sK0 + j*16, kappa + j*4);
            cp16(sP0 + j*16, phi   + j*4);
        }
    }
    cp_commit();

    for (int l = 0; l < NLAYERS; ++l) {
        const int buf = l & 1;
        if (l + 1 < NLAYERS) {
            const uint32_t dK = (buf ? sK0 : sK1), dP = (buf ? sP0 : sP1);
            const float* gK = kappa + (l+1)*EMB*EMB;
            const float* gP = phi   + (l+1)*EMB*EMB;
            #pragma unroll
            for (int i = 0; i < 5; ++i) {
                int j = tid + i*128;
                if (j < 625) {
                    cp16(dK + j*16, gK + j*4);
                    cp16(dP + j*16, gP + j*4);
                }
            }
            cp_commit();
            cp_wait<1>();
        } else {
            cp_wait<0>();
        }
        __syncthreads();

        const int cur = l & 1, nxt = cur ^ 1;
        const float* K = wK[buf];
        const float* P = wP[buf];
        if (tid < EMB) {                       // real, f = tid
            float a0=0.f,a1=0.f,a2=0.f,a3=0.f;
            #pragma unroll
            for (int e = 0; e < 48; e += 4) {
                a0 += sar[cur][e+0]*K[(e+0)*EMB+tid] - sai[cur][e+0]*P[(e+0)*EMB+tid];
                a1 += sar[cur][e+1]*K[(e+1)*EMB+tid] - sai[cur][e+1]*P[(e+1)*EMB+tid];
                a2 += sar[cur][e+2]*K[(e+2)*EMB+tid] - sai[cur][e+2]*P[(e+2)*EMB+tid];
                a3 += sar[cur][e+3]*K[(e+3)*EMB+tid] - sai[cur][e+3]*P[(e+3)*EMB+tid];
            }
            a0 += sar[cur][48]*K[48*EMB+tid] - sai[cur][48]*P[48*EMB+tid];
            a1 += sar[cur][49]*K[49*EMB+tid] - sai[cur][49]*P[49*EMB+tid];
            sar[nxt][tid] = (a0+a1) + (a2+a3);
        } else if (tid >= 64 && tid < 64 + EMB) {  // imag, f = tid-64
            const int f = tid - 64;
            float a0=0.f,a1=0.f,a2=0.f,a3=0.f;
            #pragma unroll
            for (int e = 0; e < 48; e += 4) {
                a0 += sar[cur][e+0]*P[(e+0)*EMB+f] + sai[cur][e+0]*K[(e+0)*EMB+f];
                a1 += sar[cur][e+1]*P[(e+1)*EMB+f] + sai[cur][e+1]*K[(e+1)*EMB+f];
                a2 += sar[cur][e+2]*P[(e+2)*EMB+f] + sai[cur][e+2]*K[(e+2)*EMB+f];
                a3 += sar[cur][e+3]*P[(e+3)*EMB+f] + sai[cur][e+3]*K[(e+3)*EMB+f];
            }
            a0 += sar[cur][48]*P[48*EMB+f] + sai[cur][48]*K[48*EMB+f];
            a1 += sar[cur][49]*P[49*EMB+f] + sai[cur][49]*K[49*EMB+f];
            sai[nxt][f] = (a0+a1) + (a2+a3);
        }
        __syncthreads();
    }

    // 8 layers (even): result in buffer index 0
    if (tid < EMB) {
        float a = sar[0][tid], b = sai[0][tid];
        sint[tid] = a*a + b*b;
    }
    __syncthreads();
    if (tid < VOCAB) {
        float acc = __ldg(b_out + tid);
        #pragma unroll
        for (int e = 0; e < EMB; ++e)
            acc += sint[e] * __ldg(W_out + e*VOCAB + tid);
        // 4 shifted replicas (pads: j=0->0, 1->3, 2->2, 3->1)
        g_tab[0*REP_FLOATS + t*72 + tid + 0] = acc;
        g_tab[1*REP_FLOATS + t*72 + tid + 3] = acc;
        g_tab[2*REP_FLOATS + t*72 + tid + 2] = acc;
        g_tab[3*REP_FLOATS + t*72 + tid + 1] = acc;
    }
}

// ---------------------------------------------------------------------------
// Kernel 2: gather. One warp = 32 consecutive tokens = 2144 floats = 536
// float4s (exact). Lane owns output float4 p4 = lane + 32*i -> STG.128 is
// 512B contiguous, 128B-aligned per warp. Streaming .cs stores: the 140MB
// output exceeds L2 (126MB); evict-first protects the table's L2 residency
// (verified: write-back regressed 24.2 -> 34.9us in R6).
// Token ids packed two-per-register so each iteration needs ONE shfl.
// Main table read = one aligned LDG.128 from the matching shifted replica;
// straddles (r>=64) take one predicated fixup LDG.
// ---------------------------------------------------------------------------
__device__ __forceinline__ void stcs128(float4* p, float4 v) {
    asm volatile("st.global.cs.v4.f32 [%0], {%1,%2,%3,%4};"
                 :: "l"(p), "f"(v.x), "f"(v.y), "f"(v.z), "f"(v.w) : "memory");
}

__global__ void __launch_bounds__(256) gather_kernel(
    const int* __restrict__ idx, float* __restrict__ out)
{
    const int lane = threadIdx.x & 31;
    const int warp = (blockIdx.x * 256 + (int)threadIdx.x) >> 5;   // 0..16383

    const int mytok = __ldg(idx + warp*32 + lane);       // token ids < 67 (8 bits)
    const int nxt   = __shfl_down_sync(0xffffffffu, mytok, 1);
    const int pair  = mytok | (nxt << 8);                // {tok[lane], tok[lane+1]}
    float4* O = (float4*)out + (uint32_t)warp * 536;

    #pragma unroll
    for (int i = 0; i < 17; ++i) {
        const int p4 = lane + 32*i;          // output float4 index
        const int e0 = 4*p4;
        const int tk = (int)((unsigned)e0 / 67u);  // owning token slot
        const int r  = e0 - 67*tk;           // element offset within token row

        const int pp     = __shfl_sync(0xffffffffu, pair, tk & 31);
        const int token  = pp & 0xff;
        const int token2 = (pp >> 8) & 0xff;

        const int j   = tk & 3;              // == r & 3 (e0 % 4 == 0)
        const int pos = (r + 3) & ~3;        // r + pad_j, 16B-aligned
        float4 v = __ldg((const float4*)(g_tab + j*REP_FLOATS + token*72 + pos));

        if (r >= 64) {                       // straddle: tail from next token
            float4 w = __ldg((const float4*)(g_tab + (j+1)*REP_FLOATS + token2*72));
            if (r == 66) v.y = w.y;
            if (r >= 65) v.z = w.z;
            v.w = w.w;
        }
        if (i < 16 || lane < 24)             // quads >=536 don't exist (i=16, lanes 24-31)
            stcs128(O + p4, v);
    }
}

// ---------------------------------------------------------------------------
// Launch
// ---------------------------------------------------------------------------
extern "C" void kernel_launch(void* const* d_in, const int* in_sizes, int n_in,
                              void* d_out, int out_size) {
    const int*   idx = (const int*)d_in[0];   // input_seq [64,8192] int32
    const float* emb = (const float*)d_in[1]; // embedding_table [67,50]
    const float* kap = (const float*)d_in[2]; // kappa [8,50,50]
    const float* ph  = (const float*)d_in[3]; // phi   [8,50,50]
    const float* Wo  = (const float*)d_in[4]; // W_out [50,67]
    const float* bo  = (const float*)d_in[5]; // b_out [67]
    float* out = (float*)d_out;

    table_kernel<<<VOCAB, 128>>>(emb, kap, ph, Wo, bo);
    gather_kernel<<<2048, 256>>>(idx, out);   // 16384 warps, 32 tokens each
}